// round 2
// baseline (speedup 1.0000x reference)
#include <cuda_runtime.h>
#include <math.h>

#define BB   4
#define NN   10000
#define FIN  64
#define UU   64
#define EE   160000
#define CC   128        // FIN + UU
#define HID  384        // MAX_VIEW * CC
#define NBC  (BB*NN)    // 40000 rows

// ---------------- scratch (device globals; no runtime allocation) -----------
__device__ float g_x [BB*NN*CC];   // x_ru  (B,N,C)
__device__ float g_y1[BB*NN*CC];   // A x
__device__ float g_y2[BB*NN*CC];   // A^2 x
__device__ float g_xc[BB*NN*CC];   // x_c
__device__ float g_u [BB*NN*UU];   // u gate
__device__ int   g_counts [NN];
__device__ int   g_offsets[NN+1];
__device__ int   g_cursor [NN];
__device__ int   g_perm   [EE];

// ---------------- CSR build --------------------------------------------------
__global__ void zero_counts_k() {
    int i = blockIdx.x * blockDim.x + threadIdx.x;
    if (i < NN) g_counts[i] = 0;
}

__global__ void count_k(const int* __restrict__ dst) {
    int e = blockIdx.x * blockDim.x + threadIdx.x;
    if (e < EE) atomicAdd(&g_counts[dst[e]], 1);
}

// single-block exclusive scan of 10000 counts (chunked Hillis-Steele)
__global__ void scan_k() {
    const int CHUNK = (NN + 1023) / 1024;  // 10
    __shared__ int sums[1024];
    int t = threadIdx.x;
    int base = t * CHUNK;
    int local[CHUNK];
    int s = 0;
    #pragma unroll
    for (int i = 0; i < CHUNK; i++) {
        int idx = base + i;
        int v = (idx < NN) ? g_counts[idx] : 0;
        local[i] = v; s += v;
    }
    sums[t] = s;
    __syncthreads();
    for (int off = 1; off < 1024; off <<= 1) {
        int v = (t >= off) ? sums[t - off] : 0;
        __syncthreads();
        sums[t] += v;
        __syncthreads();
    }
    int prefix = (t == 0) ? 0 : sums[t - 1];
    #pragma unroll
    for (int i = 0; i < CHUNK; i++) {
        int idx = base + i;
        if (idx < NN) {
            g_offsets[idx] = prefix;
            g_cursor[idx]  = prefix;
            prefix += local[i];
        }
    }
    if (t == 1023) g_offsets[NN] = sums[1023];
}

__global__ void fill_k(const int* __restrict__ dst) {
    int e = blockIdx.x * blockDim.x + threadIdx.x;
    if (e < EE) {
        int pos = atomicAdd(&g_cursor[dst[e]], 1);
        g_perm[pos] = e;
    }
}

// ---------------- concat(inputs, hx) -> g_x ----------------------------------
__global__ void concat_k(const float* __restrict__ in, const float* __restrict__ hx) {
    int idx = blockIdx.x * blockDim.x + threadIdx.x;
    if (idx >= BB*NN*CC) return;
    int c  = idx & (CC - 1);
    int bn = idx >> 7;
    g_x[idx] = (c < FIN) ? in[bn*FIN + c] : hx[bn*UU + (c - FIN)];
}

// ---------------- sparse propagation: y[:,n,:] = sum_e ker[e]*x[:,src[e],:] --
// one block per destination node, 128 threads = channels, 4 batch accumulators
__global__ void prop_k(const float* __restrict__ x, float* __restrict__ y,
                       const int* __restrict__ src, const float* __restrict__ ker) {
    int n = blockIdx.x;
    int c = threadIdx.x;
    int s0 = g_offsets[n];
    int s1 = g_offsets[n + 1];
    __shared__ int   es[128];
    __shared__ float ks[128];
    float a0 = 0.f, a1 = 0.f, a2 = 0.f, a3 = 0.f;
    for (int base = s0; base < s1; base += 128) {
        int cnt = min(128, s1 - base);
        if (c < cnt) {
            int e = g_perm[base + c];
            es[c] = src[e];
            ks[c] = ker[e];
        }
        __syncthreads();
        #pragma unroll 4
        for (int i = 0; i < cnt; i++) {
            int   sidx = es[i];
            float k    = ks[i];
            const float* xp = x + sidx * CC + c;
            a0 += k * xp[0 * NN * CC];
            a1 += k * xp[1 * NN * CC];
            a2 += k * xp[2 * NN * CC];
            a3 += k * xp[3 * NN * CC];
        }
        __syncthreads();
    }
    float* yp = y + n * CC + c;
    yp[0 * NN * CC] = a0;
    yp[1 * NN * CC] = a1;
    yp[2 * NN * CC] = a2;
    yp[3 * NN * CC] = a3;
}

// ---------------- ru GEMM + gates: 16 rows/block, 128 outputs/thread-col -----
#define NPB 16
__global__ void ru_k(const float* __restrict__ Wru, const float* __restrict__ bru,
                     const float* __restrict__ inputs, const float* __restrict__ hx) {
    __shared__ float hs[NPB][HID];
    int t    = threadIdx.x;          // 0..127 (output column)
    int base = blockIdx.x * NPB;     // row index in [0, B*N)
    // stage h = [x | y1 | y2]
    for (int idx = t; idx < NPB * HID; idx += 128) {
        int i  = idx / HID;
        int k  = idx - i * HID;
        int bn = base + i;
        float v;
        if      (k < CC)     v = g_x [bn*CC + k];
        else if (k < 2*CC)   v = g_y1[bn*CC + (k - CC)];
        else                 v = g_y2[bn*CC + (k - 2*CC)];
        hs[i][k] = v;
    }
    __syncthreads();
    float acc[NPB];
    float bias = bru[t];
    #pragma unroll
    for (int i = 0; i < NPB; i++) acc[i] = bias;
    #pragma unroll 4
    for (int k = 0; k < HID; k++) {
        float w = Wru[k * 128 + t];
        #pragma unroll
        for (int i = 0; i < NPB; i++) acc[i] += hs[i][k] * w;
    }
    #pragma unroll
    for (int i = 0; i < NPB; i++) {
        int bn = base + i;
        float s = 1.f / (1.f + __expf(-acc[i]));
        if (t < UU) {                         // r gate -> x_c[:, FIN + t] = r * hx
            g_xc[bn*CC + FIN + t] = s * hx[bn*UU + t];
        } else {                              // u gate
            g_u[bn*UU + (t - UU)] = s;
        }
    }
    // x_c first half = inputs
    for (int idx = t; idx < NPB * FIN; idx += 128) {
        int i = idx / FIN, c2 = idx % FIN;
        int bn = base + i;
        g_xc[bn*CC + c2] = inputs[bn*FIN + c2];
    }
}

// ---------------- candidate GEMM + output ------------------------------------
__global__ void cout_k(const float* __restrict__ Wc, const float* __restrict__ bc,
                       const float* __restrict__ hx, float* __restrict__ out) {
    __shared__ float hs[NPB][HID];
    int t    = threadIdx.x;          // 0..63
    int base = blockIdx.x * NPB;
    for (int idx = t; idx < NPB * HID; idx += 64) {
        int i  = idx / HID;
        int k  = idx - i * HID;
        int bn = base + i;
        float v;
        if      (k < CC)     v = g_xc[bn*CC + k];
        else if (k < 2*CC)   v = g_y1[bn*CC + (k - CC)];
        else                 v = g_y2[bn*CC + (k - 2*CC)];
        hs[i][k] = v;
    }
    __syncthreads();
    float acc[NPB];
    float bias = bc[t];
    #pragma unroll
    for (int i = 0; i < NPB; i++) acc[i] = bias;
    #pragma unroll 4
    for (int k = 0; k < HID; k++) {
        float w = Wc[k * 64 + t];
        #pragma unroll
        for (int i = 0; i < NPB; i++) acc[i] += hs[i][k] * w;
    }
    #pragma unroll
    for (int i = 0; i < NPB; i++) {
        int bn = base + i;
        float cval = tanhf(acc[i]);
        float uval = g_u[bn*UU + t];
        float hval = hx[bn*UU + t];
        out[bn*UU + t] = uval * hval + (1.f - uval) * cval;
    }
}

// ---------------- launch ------------------------------------------------------
extern "C" void kernel_launch(void* const* d_in, const int* in_sizes, int n_in,
                              void* d_out, int out_size) {
    const float* inputs = (const float*)d_in[0];
    const float* hx     = (const float*)d_in[1];
    const int*   sidx   = (const int*)  d_in[2];   // (2, E): row0=src, row1=dst
    const float* ker    = (const float*)d_in[3];
    const float* W_ru   = (const float*)d_in[4];
    const float* b_ru   = (const float*)d_in[5];
    const float* W_c    = (const float*)d_in[6];
    const float* b_c    = (const float*)d_in[7];
    float*       out    = (float*)d_out;

    const int* src = sidx;
    const int* dst = sidx + EE;

    // CSR build
    zero_counts_k<<<(NN + 255) / 256, 256>>>();
    count_k<<<(EE + 255) / 256, 256>>>(dst);
    scan_k<<<1, 1024>>>();
    fill_k<<<(EE + 255) / 256, 256>>>(dst);

    // x_ru = concat(inputs, hx)
    concat_k<<<(BB*NN*CC + 255) / 256, 256>>>(inputs, hx);

    // views for ru
    { float *px, *py1, *py2, *pxc;
      cudaGetSymbolAddress((void**)&px,  g_x);
      cudaGetSymbolAddress((void**)&py1, g_y1);
      cudaGetSymbolAddress((void**)&py2, g_y2);
      cudaGetSymbolAddress((void**)&pxc, g_xc);

      prop_k<<<NN, 128>>>(px,  py1, src, ker);
      prop_k<<<NN, 128>>>(py1, py2, src, ker);

      // ru gates + build x_c
      ru_k<<<NBC / NPB, 128>>>(W_ru, b_ru, inputs, hx);

      // views for candidate (reuse y buffers)
      prop_k<<<NN, 128>>>(pxc, py1, src, ker);
      prop_k<<<NN, 128>>>(py1, py2, src, ker);
    }

    // candidate + output
    cout_k<<<NBC / NPB, 64>>>(W_c, b_c, hx, out);
}

// round 4
// speedup vs baseline: 1.9695x; 1.9695x over previous
#include <cuda_runtime.h>
#include <math.h>
#include <stdint.h>

#define BB   4
#define NN   10000
#define FIN  64
#define UU   64
#define EE   160000
#define CC   128        // FIN + UU
#define HID  384        // MAX_VIEW * CC
#define NBC  (BB*NN)    // 40000 rows

// ---------------- scratch (device globals) -----------------------------------
__device__ float g_h [BB*NN*HID];   // [b*NN+n][384] : views for ru conv
__device__ float g_hc[BB*NN*HID];   // [b*NN+n][384] : views for candidate conv
__device__ float g_u [BB*NN*UU];    // u gate
__device__ int   g_counts [NN];
__device__ int   g_offsets[NN+1];
__device__ int   g_cursor [NN];
__device__ int   g_perm   [EE];

// ---------------- CSR build --------------------------------------------------
__global__ void zero_counts_k() {
    int i = blockIdx.x * blockDim.x + threadIdx.x;
    if (i < NN) g_counts[i] = 0;
}

__global__ void count_k(const int* __restrict__ dst) {
    int e = blockIdx.x * blockDim.x + threadIdx.x;
    if (e < EE) atomicAdd(&g_counts[dst[e]], 1);
}

// single-block exclusive scan of 10000 counts
__global__ void scan_k() {
    const int CHUNK = (NN + 1023) / 1024;  // 10
    __shared__ int sums[1024];
    int t = threadIdx.x;
    int base = t * CHUNK;
    int local[CHUNK];
    int s = 0;
    #pragma unroll
    for (int i = 0; i < CHUNK; i++) {
        int idx = base + i;
        int v = (idx < NN) ? g_counts[idx] : 0;
        local[i] = v; s += v;
    }
    sums[t] = s;
    __syncthreads();
    for (int off = 1; off < 1024; off <<= 1) {
        int v = (t >= off) ? sums[t - off] : 0;
        __syncthreads();
        sums[t] += v;
        __syncthreads();
    }
    int prefix = (t == 0) ? 0 : sums[t - 1];
    #pragma unroll
    for (int i = 0; i < CHUNK; i++) {
        int idx = base + i;
        if (idx < NN) {
            g_offsets[idx] = prefix;
            g_cursor[idx]  = prefix;
            prefix += local[i];
        }
    }
    if (t == 1023) g_offsets[NN] = sums[1023];
}

__global__ void fill_k(const int* __restrict__ dst) {
    int e = blockIdx.x * blockDim.x + threadIdx.x;
    if (e < EE) {
        int pos = atomicAdd(&g_cursor[dst[e]], 1);
        g_perm[pos] = e;
    }
}

// ---------------- concat: g_h view0 = [inputs|hx]; g_hc view0 lo = inputs ----
__global__ void concat_k(const float* __restrict__ in, const float* __restrict__ hx) {
    int idx = blockIdx.x * blockDim.x + threadIdx.x;
    if (idx >= BB*NN*CC) return;
    int c  = idx & (CC - 1);
    int bn = idx >> 7;
    float v = (c < FIN) ? in[bn*FIN + c] : hx[bn*UU + (c - FIN)];
    g_h[bn*HID + c] = v;
    if (c < FIN) g_hc[bn*HID + c] = v;
}

// ---------------- sparse propagation (h-major layout) ------------------------
// x, y point at the view slice: element (b, node, c) at (b*NN+node)*HID + c
__global__ void prop_k(const float* __restrict__ x, float* __restrict__ y,
                       const int* __restrict__ src, const float* __restrict__ ker) {
    int n = blockIdx.x;
    int c = threadIdx.x;
    int s0 = g_offsets[n];
    int s1 = g_offsets[n + 1];
    __shared__ int   es[128];
    __shared__ float ks[128];
    float a0 = 0.f, a1 = 0.f, a2 = 0.f, a3 = 0.f;
    const int BS = NN * HID;
    for (int base = s0; base < s1; base += 128) {
        int cnt = min(128, s1 - base);
        if (c < cnt) {
            int e = g_perm[base + c];
            es[c] = src[e];
            ks[c] = ker[e];
        }
        __syncthreads();
        #pragma unroll 4
        for (int i = 0; i < cnt; i++) {
            const float* xp = x + es[i] * HID + c;
            float k = ks[i];
            a0 += k * xp[0];
            a1 += k * xp[BS];
            a2 += k * xp[2 * BS];
            a3 += k * xp[3 * BS];
        }
        __syncthreads();
    }
    float* yp = y + n * HID + c;
    yp[0]      = a0;
    yp[BS]     = a1;
    yp[2 * BS] = a2;
    yp[3 * BS] = a3;
}

// ---------------- tf32 mma helpers -------------------------------------------
__device__ __forceinline__ uint32_t f2tf(float x) {
    uint32_t r; asm("cvt.rna.tf32.f32 %0, %1;" : "=r"(r) : "f"(x)); return r;
}
__device__ __forceinline__ void mma8(float* c, const uint32_t* a, uint32_t b0, uint32_t b1) {
    asm volatile("mma.sync.aligned.m16n8k8.row.col.f32.tf32.tf32.f32 "
        "{%0,%1,%2,%3},{%4,%5,%6,%7},{%8,%9},{%0,%1,%2,%3};"
        : "+f"(c[0]), "+f"(c[1]), "+f"(c[2]), "+f"(c[3])
        : "r"(a[0]), "r"(a[1]), "r"(a[2]), "r"(a[3]), "r"(b0), "r"(b1));
}

#define AP   36    // A smem pitch (floats)
#define WPRU 132   // W smem pitch for N=128
#define WPC  68    // W smem pitch for N=64

// ---------------- ru GEMM (40000x128x384) + gate epilogue --------------------
__global__ void ru_mma(const float* __restrict__ W, const float* __restrict__ bias,
                       const float* __restrict__ hx) {
    __shared__ uint32_t As[64 * AP];
    __shared__ uint32_t Ws[32 * WPRU];
    int tid  = threadIdx.x;
    int lane = tid & 31, warp = tid >> 5;
    int wm = warp & 3, wn = warp >> 2;       // 4x2 warp grid
    int gid = lane >> 2, tig = lane & 3;
    int rbase = blockIdx.x * 64;
    float acc[8][4] = {};
    for (int kt = 0; kt < HID / 32; kt++) {
        #pragma unroll
        for (int i = 0; i < 2; i++) {
            int slot = tid + i * 256;            // 0..511
            int r = slot >> 3, kv = slot & 7;
            float4 v = *(const float4*)&g_h[(rbase + r) * HID + kt * 32 + kv * 4];
            uint32_t* p = &As[r * AP + kv * 4];
            p[0] = f2tf(v.x); p[1] = f2tf(v.y); p[2] = f2tf(v.z); p[3] = f2tf(v.w);
        }
        #pragma unroll
        for (int i = 0; i < 4; i++) {
            int slot = tid + i * 256;            // 0..1023
            int kr = slot >> 5, nv = slot & 31;
            float4 v = *(const float4*)&W[(kt * 32 + kr) * 128 + nv * 4];
            uint32_t* p = &Ws[kr * WPRU + nv * 4];
            p[0] = f2tf(v.x); p[1] = f2tf(v.y); p[2] = f2tf(v.z); p[3] = f2tf(v.w);
        }
        __syncthreads();
        #pragma unroll
        for (int k8 = 0; k8 < 4; k8++) {
            int ko = k8 * 8;
            uint32_t a[4];
            a[0] = As[(wm * 16 + gid    ) * AP + ko + tig];
            a[1] = As[(wm * 16 + gid + 8) * AP + ko + tig];
            a[2] = As[(wm * 16 + gid    ) * AP + ko + tig + 4];
            a[3] = As[(wm * 16 + gid + 8) * AP + ko + tig + 4];
            #pragma unroll
            for (int j = 0; j < 8; j++) {
                int n = wn * 64 + j * 8 + gid;
                uint32_t b0 = Ws[(ko + tig    ) * WPRU + n];
                uint32_t b1 = Ws[(ko + tig + 4) * WPRU + n];
                mma8(acc[j], a, b0, b1);
            }
        }
        __syncthreads();
    }
    // epilogue: sigmoid; col<64 -> r gate feeds x_c, else u gate
    #pragma unroll
    for (int j = 0; j < 8; j++) {
        #pragma unroll
        for (int q = 0; q < 4; q++) {
            int row = rbase + wm * 16 + gid + ((q >> 1) * 8);
            int col = wn * 64 + j * 8 + tig * 2 + (q & 1);
            float v = acc[j][q] + bias[col];
            float s = 1.f / (1.f + __expf(-v));
            if (col < UU) g_hc[row * HID + FIN + col] = s * hx[row * UU + col];
            else          g_u[row * UU + (col - UU)]  = s;
        }
    }
}

// ---------------- candidate GEMM (40000x64x384) + output ---------------------
__global__ void cout_mma(const float* __restrict__ W, const float* __restrict__ bias,
                         const float* __restrict__ hx, float* __restrict__ out) {
    __shared__ uint32_t As[64 * AP];
    __shared__ uint32_t Ws[32 * WPC];
    int tid  = threadIdx.x;
    int lane = tid & 31, warp = tid >> 5;
    int wm = warp & 3, wn = warp >> 2;
    int gid = lane >> 2, tig = lane & 3;
    int rbase = blockIdx.x * 64;
    float acc[4][4] = {};
    for (int kt = 0; kt < HID / 32; kt++) {
        #pragma unroll
        for (int i = 0; i < 2; i++) {
            int slot = tid + i * 256;
            int r = slot >> 3, kv = slot & 7;
            float4 v = *(const float4*)&g_hc[(rbase + r) * HID + kt * 32 + kv * 4];
            uint32_t* p = &As[r * AP + kv * 4];
            p[0] = f2tf(v.x); p[1] = f2tf(v.y); p[2] = f2tf(v.z); p[3] = f2tf(v.w);
        }
        #pragma unroll
        for (int i = 0; i < 2; i++) {
            int slot = tid + i * 256;            // 0..511
            int kr = slot >> 4, nv = slot & 15;
            float4 v = *(const float4*)&W[(kt * 32 + kr) * 64 + nv * 4];
            uint32_t* p = &Ws[kr * WPC + nv * 4];
            p[0] = f2tf(v.x); p[1] = f2tf(v.y); p[2] = f2tf(v.z); p[3] = f2tf(v.w);
        }
        __syncthreads();
        #pragma unroll
        for (int k8 = 0; k8 < 4; k8++) {
            int ko = k8 * 8;
            uint32_t a[4];
            a[0] = As[(wm * 16 + gid    ) * AP + ko + tig];
            a[1] = As[(wm * 16 + gid + 8) * AP + ko + tig];
            a[2] = As[(wm * 16 + gid    ) * AP + ko + tig + 4];
            a[3] = As[(wm * 16 + gid + 8) * AP + ko + tig + 4];
            #pragma unroll
            for (int j = 0; j < 4; j++) {
                int n = wn * 32 + j * 8 + gid;
                uint32_t b0 = Ws[(ko + tig    ) * WPC + n];
                uint32_t b1 = Ws[(ko + tig + 4) * WPC + n];
                mma8(acc[j], a, b0, b1);
            }
        }
        __syncthreads();
    }
    #pragma unroll
    for (int j = 0; j < 4; j++) {
        #pragma unroll
        for (int q = 0; q < 4; q++) {
            int row = rbase + wm * 16 + gid + ((q >> 1) * 8);
            int col = wn * 32 + j * 8 + tig * 2 + (q & 1);
            float v = acc[j][q] + bias[col];
            float c = tanhf(v);
            float u = g_u[row * UU + col];
            float h = hx[row * UU + col];
            out[row * UU + col] = u * h + (1.f - u) * c;
        }
    }
}

// ---------------- launch ------------------------------------------------------
extern "C" void kernel_launch(void* const* d_in, const int* in_sizes, int n_in,
                              void* d_out, int out_size) {
    const float* inputs = (const float*)d_in[0];
    const float* hx     = (const float*)d_in[1];
    const int*   sidx   = (const int*)  d_in[2];
    const float* ker    = (const float*)d_in[3];
    const float* W_ru   = (const float*)d_in[4];
    const float* b_ru   = (const float*)d_in[5];
    const float* W_c    = (const float*)d_in[6];
    const float* b_c    = (const float*)d_in[7];
    float*       out    = (float*)d_out;

    const int* src = sidx;
    const int* dst = sidx + EE;

    zero_counts_k<<<(NN + 255) / 256, 256>>>();
    count_k<<<(EE + 255) / 256, 256>>>(dst);
    scan_k<<<1, 1024>>>();
    fill_k<<<(EE + 255) / 256, 256>>>(dst);

    concat_k<<<(BB*NN*CC + 255) / 256, 256>>>(inputs, hx);

    float *ph, *phc;
    cudaGetSymbolAddress((void**)&ph,  g_h);
    cudaGetSymbolAddress((void**)&phc, g_hc);

    prop_k<<<NN, 128>>>(ph,        ph  + CC,   src, ker);   // view1 = A x
    prop_k<<<NN, 128>>>(ph  + CC,  ph  + 2*CC, src, ker);   // view2 = A^2 x

    ru_mma<<<NBC / 64, 256>>>(W_ru, b_ru, hx);              // gates + x_c hi half

    prop_k<<<NN, 128>>>(phc,       phc + CC,   src, ker);
    prop_k<<<NN, 128>>>(phc + CC,  phc + 2*CC, src, ker);

    cout_mma<<<NBC / 64, 256>>>(W_c, b_c, hx, out);
}

// round 5
// speedup vs baseline: 2.1896x; 1.1118x over previous
#include <cuda_runtime.h>
#include <cuda_fp16.h>
#include <math.h>
#include <stdint.h>

#define BB   4
#define NN   10000
#define FIN  64
#define UU   64
#define EE   160000
#define CC   128        // FIN + UU
#define HID  384        // MAX_VIEW * CC     (ru GEMM K)
#define HCW  192        // candidate-only channels: [r*hx | A rhx | A^2 rhx]
#define NBC  (BB*NN)    // 40000 rows

// ---------------- scratch (device globals) -----------------------------------
__device__ float   g_h [BB*NN*HID];   // fp32 views for ru GEMM
__device__ float   g_hc[BB*NN*HCW];   // fp32 candidate-only views
__device__ float   g_u [BB*NN*UU];    // u gate
__device__ __half2 g_f0[BB*NN*64];    // fp16 mirror: [in|hx]      (prop1 input)
__device__ __half2 g_f1[BB*NN*64];    // fp16 mirror: A[in|hx]     (prop2 input)
__device__ __half  g_c0[BB*NN*64];    // fp16 mirror: r*hx         (prop3 input)
__device__ __half2 g_c1[BB*NN*32];    // fp16 mirror: A(r*hx)      (prop4 input)
__device__ int     g_counts [NN];
__device__ int     g_offsets[NN+1];
__device__ int     g_cursor [NN];
__device__ int     g_srcs   [EE];     // src node per CSR slot
__device__ float   g_kers   [EE];     // kernel weight per CSR slot

// ---------------- CSR build --------------------------------------------------
__global__ void zero_counts_k() {
    int i = blockIdx.x * blockDim.x + threadIdx.x;
    if (i < NN) g_counts[i] = 0;
}

__global__ void count_k(const int* __restrict__ dst) {
    int e = blockIdx.x * blockDim.x + threadIdx.x;
    if (e < EE) atomicAdd(&g_counts[dst[e]], 1);
}

__global__ void scan_k() {
    const int CHUNK = (NN + 1023) / 1024;  // 10
    __shared__ int sums[1024];
    int t = threadIdx.x;
    int base = t * CHUNK;
    int local[CHUNK];
    int s = 0;
    #pragma unroll
    for (int i = 0; i < CHUNK; i++) {
        int idx = base + i;
        int v = (idx < NN) ? g_counts[idx] : 0;
        local[i] = v; s += v;
    }
    sums[t] = s;
    __syncthreads();
    for (int off = 1; off < 1024; off <<= 1) {
        int v = (t >= off) ? sums[t - off] : 0;
        __syncthreads();
        sums[t] += v;
        __syncthreads();
    }
    int prefix = (t == 0) ? 0 : sums[t - 1];
    #pragma unroll
    for (int i = 0; i < CHUNK; i++) {
        int idx = base + i;
        if (idx < NN) {
            g_offsets[idx] = prefix;
            g_cursor[idx]  = prefix;
            prefix += local[i];
        }
    }
    if (t == 1023) g_offsets[NN] = sums[1023];
}

__global__ void fill_k(const int* __restrict__ src, const int* __restrict__ dst,
                       const float* __restrict__ ker) {
    int e = blockIdx.x * blockDim.x + threadIdx.x;
    if (e < EE) {
        int pos = atomicAdd(&g_cursor[dst[e]], 1);
        g_srcs[pos] = src[e];
        g_kers[pos] = ker[e];
    }
}

// ---------------- concat: g_h view0 = [in|hx] (fp32) + g_f0 (fp16) -----------
__global__ void concat_k(const float* __restrict__ in, const float* __restrict__ hx) {
    int idx = blockIdx.x * blockDim.x + threadIdx.x;      // over B*NN*64 half2
    if (idx >= BB*NN*64) return;
    int c2 = idx & 63;
    int bn = idx >> 6;
    float v0, v1;
    if (c2 < 32) { v0 = in[bn*FIN + c2*2];        v1 = in[bn*FIN + c2*2 + 1]; }
    else         { v0 = hx[bn*UU + (c2-32)*2];    v1 = hx[bn*UU + (c2-32)*2 + 1]; }
    g_h[bn*HID + c2*2]     = v0;
    g_h[bn*HID + c2*2 + 1] = v1;
    g_f0[idx] = __floats2half2_rn(v0, v1);
}

// ---------------- 128-wide propagation (fp16 gather, fp32 out) ---------------
// 2 warps per node, thread t in 0..63 = half2 channel. Edge list staged via shfl.
__global__ void prop128_k(const __half2* __restrict__ x2,  // [B][NN][64]
                          float* __restrict__ yf, int ycol,
                          __half2* __restrict__ y2) {
    int n    = blockIdx.x * 2 + (threadIdx.x >> 6);
    int t    = threadIdx.x & 63;
    int lane = threadIdx.x & 31;
    int s0 = g_offsets[n], s1 = g_offsets[n + 1];
    const int BS = NN * 64;
    float2 a0 = {0,0}, a1 = {0,0}, a2 = {0,0}, a3 = {0,0};
    for (int base = s0; base < s1; base += 32) {
        int cnt = min(32, s1 - base);
        int sv = 0; float kv = 0.f;
        if (lane < cnt) { sv = g_srcs[base + lane]; kv = g_kers[base + lane]; }
        for (int i = 0; i < cnt; i++) {
            int   s = __shfl_sync(0xffffffffu, sv, i);
            float k = __shfl_sync(0xffffffffu, kv, i);
            const __half2* xp = x2 + s * 64 + t;
            float2 v0 = __half22float2(xp[0]);
            float2 v1 = __half22float2(xp[BS]);
            float2 v2 = __half22float2(xp[2*BS]);
            float2 v3 = __half22float2(xp[3*BS]);
            a0.x += k*v0.x; a0.y += k*v0.y;
            a1.x += k*v1.x; a1.y += k*v1.y;
            a2.x += k*v2.x; a2.y += k*v2.y;
            a3.x += k*v3.x; a3.y += k*v3.y;
        }
    }
    float2 acc[4] = {a0, a1, a2, a3};
    #pragma unroll
    for (int b = 0; b < 4; b++) {
        float* yp = yf + (b*NN + n) * HID + ycol + t*2;
        yp[0] = acc[b].x; yp[1] = acc[b].y;
        if (y2) y2[b*BS + n*64 + t] = __floats2half2_rn(acc[b].x, acc[b].y);
    }
}

// ---------------- 64-wide propagation (candidate r*hx channels) --------------
// 1 warp per node, lane = half2 channel.
__global__ void prop64_k(const __half2* __restrict__ x2,   // [B][NN][32]
                         float* __restrict__ yf, int ycol,
                         __half2* __restrict__ y2) {
    int n    = blockIdx.x * 4 + (threadIdx.x >> 5);
    int lane = threadIdx.x & 31;
    int s0 = g_offsets[n], s1 = g_offsets[n + 1];
    const int BS = NN * 32;
    float2 a0 = {0,0}, a1 = {0,0}, a2 = {0,0}, a3 = {0,0};
    for (int base = s0; base < s1; base += 32) {
        int cnt = min(32, s1 - base);
        int sv = 0; float kv = 0.f;
        if (lane < cnt) { sv = g_srcs[base + lane]; kv = g_kers[base + lane]; }
        for (int i = 0; i < cnt; i++) {
            int   s = __shfl_sync(0xffffffffu, sv, i);
            float k = __shfl_sync(0xffffffffu, kv, i);
            const __half2* xp = x2 + s * 32 + lane;
            float2 v0 = __half22float2(xp[0]);
            float2 v1 = __half22float2(xp[BS]);
            float2 v2 = __half22float2(xp[2*BS]);
            float2 v3 = __half22float2(xp[3*BS]);
            a0.x += k*v0.x; a0.y += k*v0.y;
            a1.x += k*v1.x; a1.y += k*v1.y;
            a2.x += k*v2.x; a2.y += k*v2.y;
            a3.x += k*v3.x; a3.y += k*v3.y;
        }
    }
    float2 acc[4] = {a0, a1, a2, a3};
    #pragma unroll
    for (int b = 0; b < 4; b++) {
        float* yp = yf + (b*NN + n) * HCW + ycol + lane*2;
        yp[0] = acc[b].x; yp[1] = acc[b].y;
        if (y2) y2[b*BS + n*32 + lane] = __floats2half2_rn(acc[b].x, acc[b].y);
    }
}

// ---------------- tf32 mma helpers -------------------------------------------
__device__ __forceinline__ uint32_t f2tf(float x) {
    uint32_t r; asm("cvt.rna.tf32.f32 %0, %1;" : "=r"(r) : "f"(x)); return r;
}
__device__ __forceinline__ void mma8(float* c, const uint32_t* a, uint32_t b0, uint32_t b1) {
    asm volatile("mma.sync.aligned.m16n8k8.row.col.f32.tf32.tf32.f32 "
        "{%0,%1,%2,%3},{%4,%5,%6,%7},{%8,%9},{%0,%1,%2,%3};"
        : "+f"(c[0]), "+f"(c[1]), "+f"(c[2]), "+f"(c[3])
        : "r"(a[0]), "r"(a[1]), "r"(a[2]), "r"(a[3]), "r"(b0), "r"(b1));
}

#define AP   36
#define WPRU 132
#define WPC  68

// ---------------- ru GEMM (40000x128x384) + gate epilogue --------------------
__global__ void ru_mma(const float* __restrict__ W, const float* __restrict__ bias,
                       const float* __restrict__ hx) {
    __shared__ uint32_t As[64 * AP];
    __shared__ uint32_t Ws[32 * WPRU];
    int tid  = threadIdx.x;
    int lane = tid & 31, warp = tid >> 5;
    int wm = warp & 3, wn = warp >> 2;
    int gid = lane >> 2, tig = lane & 3;
    int rbase = blockIdx.x * 64;
    float acc[8][4] = {};
    for (int kt = 0; kt < HID / 32; kt++) {
        #pragma unroll
        for (int i = 0; i < 2; i++) {
            int slot = tid + i * 256;
            int r = slot >> 3, kv = slot & 7;
            float4 v = *(const float4*)&g_h[(rbase + r) * HID + kt * 32 + kv * 4];
            uint32_t* p = &As[r * AP + kv * 4];
            p[0] = f2tf(v.x); p[1] = f2tf(v.y); p[2] = f2tf(v.z); p[3] = f2tf(v.w);
        }
        #pragma unroll
        for (int i = 0; i < 4; i++) {
            int slot = tid + i * 256;
            int kr = slot >> 5, nv = slot & 31;
            float4 v = *(const float4*)&W[(kt * 32 + kr) * 128 + nv * 4];
            uint32_t* p = &Ws[kr * WPRU + nv * 4];
            p[0] = f2tf(v.x); p[1] = f2tf(v.y); p[2] = f2tf(v.z); p[3] = f2tf(v.w);
        }
        __syncthreads();
        #pragma unroll
        for (int k8 = 0; k8 < 4; k8++) {
            int ko = k8 * 8;
            uint32_t a[4];
            a[0] = As[(wm * 16 + gid    ) * AP + ko + tig];
            a[1] = As[(wm * 16 + gid + 8) * AP + ko + tig];
            a[2] = As[(wm * 16 + gid    ) * AP + ko + tig + 4];
            a[3] = As[(wm * 16 + gid + 8) * AP + ko + tig + 4];
            #pragma unroll
            for (int j = 0; j < 8; j++) {
                int n = wn * 64 + j * 8 + gid;
                uint32_t b0 = Ws[(ko + tig    ) * WPRU + n];
                uint32_t b1 = Ws[(ko + tig + 4) * WPRU + n];
                mma8(acc[j], a, b0, b1);
            }
        }
        __syncthreads();
    }
    #pragma unroll
    for (int j = 0; j < 8; j++) {
        #pragma unroll
        for (int q = 0; q < 4; q++) {
            int row = rbase + wm * 16 + gid + ((q >> 1) * 8);
            int col = wn * 64 + j * 8 + tig * 2 + (q & 1);
            float v = acc[j][q] + bias[col];
            float s = 1.f / (1.f + __expf(-v));
            if (col < UU) {
                float rv = s * hx[row * UU + col];
                g_hc[row * HCW + col] = rv;            // r*hx fp32
                g_c0[row * 64 + col]  = __float2half(rv);  // fp16 mirror for prop3
            } else {
                g_u[row * UU + (col - UU)] = s;
            }
        }
    }
}

// ---------------- candidate GEMM (40000x64x384) + output ---------------------
// K-tile source map (kt = 0..11, 32-wide tiles):
//   pair=kt>>1: 0 in(g_h,0) 1 rhx(g_hc,0) 2 A.in(g_h,128) 3 A.rhx(g_hc,64)
//               4 A2.in(g_h,256) 5 A2.rhx(g_hc,128)
__global__ void cout_mma(const float* __restrict__ W, const float* __restrict__ bias,
                         const float* __restrict__ hx, float* __restrict__ out) {
    __shared__ uint32_t As[64 * AP];
    __shared__ uint32_t Ws[32 * WPC];
    int tid  = threadIdx.x;
    int lane = tid & 31, warp = tid >> 5;
    int wm = warp & 3, wn = warp >> 2;
    int gid = lane >> 2, tig = lane & 3;
    int rbase = blockIdx.x * 64;
    float acc[4][4] = {};
    for (int kt = 0; kt < HID / 32; kt++) {
        int pair = kt >> 1, sub = kt & 1;
        const float* srcp; int stride, colb;
        if ((pair & 1) == 0) { srcp = g_h;  stride = HID; colb = (pair >> 1) * 128 + sub * 32; }
        else                 { srcp = g_hc; stride = HCW; colb = (pair >> 1) * 64  + sub * 32; }
        #pragma unroll
        for (int i = 0; i < 2; i++) {
            int slot = tid + i * 256;
            int r = slot >> 3, kv = slot & 7;
            float4 v = *(const float4*)&srcp[(rbase + r) * stride + colb + kv * 4];
            uint32_t* p = &As[r * AP + kv * 4];
            p[0] = f2tf(v.x); p[1] = f2tf(v.y); p[2] = f2tf(v.z); p[3] = f2tf(v.w);
        }
        #pragma unroll
        for (int i = 0; i < 2; i++) {
            int slot = tid + i * 256;
            int kr = slot >> 4, nv = slot & 15;
            float4 v = *(const float4*)&W[(kt * 32 + kr) * 64 + nv * 4];
            uint32_t* p = &Ws[kr * WPC + nv * 4];
            p[0] = f2tf(v.x); p[1] = f2tf(v.y); p[2] = f2tf(v.z); p[3] = f2tf(v.w);
        }
        __syncthreads();
        #pragma unroll
        for (int k8 = 0; k8 < 4; k8++) {
            int ko = k8 * 8;
            uint32_t a[4];
            a[0] = As[(wm * 16 + gid    ) * AP + ko + tig];
            a[1] = As[(wm * 16 + gid + 8) * AP + ko + tig];
            a[2] = As[(wm * 16 + gid    ) * AP + ko + tig + 4];
            a[3] = As[(wm * 16 + gid + 8) * AP + ko + tig + 4];
            #pragma unroll
            for (int j = 0; j < 4; j++) {
                int n = wn * 32 + j * 8 + gid;
                uint32_t b0 = Ws[(ko + tig    ) * WPC + n];
                uint32_t b1 = Ws[(ko + tig + 4) * WPC + n];
                mma8(acc[j], a, b0, b1);
            }
        }
        __syncthreads();
    }
    #pragma unroll
    for (int j = 0; j < 4; j++) {
        #pragma unroll
        for (int q = 0; q < 4; q++) {
            int row = rbase + wm * 16 + gid + ((q >> 1) * 8);
            int col = wn * 32 + j * 8 + tig * 2 + (q & 1);
            float v = acc[j][q] + bias[col];
            float c = tanhf(v);
            float u = g_u[row * UU + col];
            float h = hx[row * UU + col];
            out[row * UU + col] = u * h + (1.f - u) * c;
        }
    }
}

// ---------------- launch ------------------------------------------------------
extern "C" void kernel_launch(void* const* d_in, const int* in_sizes, int n_in,
                              void* d_out, int out_size) {
    const float* inputs = (const float*)d_in[0];
    const float* hx     = (const float*)d_in[1];
    const int*   sidx   = (const int*)  d_in[2];
    const float* ker    = (const float*)d_in[3];
    const float* W_ru   = (const float*)d_in[4];
    const float* b_ru   = (const float*)d_in[5];
    const float* W_c    = (const float*)d_in[6];
    const float* b_c    = (const float*)d_in[7];
    float*       out    = (float*)d_out;

    const int* src = sidx;
    const int* dst = sidx + EE;

    zero_counts_k<<<(NN + 255) / 256, 256>>>();
    count_k<<<(EE + 255) / 256, 256>>>(dst);
    scan_k<<<1, 1024>>>();
    fill_k<<<(EE + 255) / 256, 256>>>(src, dst, ker);

    concat_k<<<(BB*NN*64 + 255) / 256, 256>>>(inputs, hx);

    float *ph, *phc; __half2 *pf0, *pf1, *pc1; __half *pc0;
    cudaGetSymbolAddress((void**)&ph,  g_h);
    cudaGetSymbolAddress((void**)&phc, g_hc);
    cudaGetSymbolAddress((void**)&pf0, g_f0);
    cudaGetSymbolAddress((void**)&pf1, g_f1);
    cudaGetSymbolAddress((void**)&pc0, g_c0);
    cudaGetSymbolAddress((void**)&pc1, g_c1);

    prop128_k<<<NN/2, 128>>>(pf0, ph, 128, pf1);          // view1 = A[in|hx]
    prop128_k<<<NN/2, 128>>>(pf1, ph, 256, nullptr);      // view2 = A^2[in|hx]

    ru_mma<<<NBC/64, 256>>>(W_ru, b_ru, hx);              // gates, r*hx, fp16 mirror

    prop64_k<<<NN/4, 128>>>((const __half2*)pc0, phc, 64,  pc1);   // A(r*hx)
    prop64_k<<<NN/4, 128>>>(pc1,              phc, 128, nullptr);  // A^2(r*hx)

    cout_mma<<<NBC/64, 256>>>(W_c, b_c, hx, out);
}